// round 10
// baseline (speedup 1.0000x reference)
#include <cuda_runtime.h>
#include <math.h>

#define NN 4096
#define HH 64
#define HC 128          // concatenated row width: [h0(64) | h1(64)]
#define G4 256
#define TT 48
#define INP 2
#define PP 12
#define RPB 16          // rows per block
#define NTH 512         // 16 warps: 2 k-halves x (4 row groups x 2 col halves)
#define ZS 34           // shared z stride per k in floats (32 duplicated + 2 pad) -> 17 ull
#define SMEM_FUSED ((256 * ZS + 2 * RPB * G4) * 4)   // z tile (34.8KB) + 2 comb (32KB)
#define MAXNNZ (1 << 21)

typedef unsigned long long ull;

// ---------------- static device scratch ----------------
__device__ float d_hcat[2][NN * HC];        // ping-pong [h0 | h1] per node
__device__ float d_c0[NN * HH];
__device__ float d_c1[NN * HH];
__device__ float d_Xall[NN * (TT * INP)];   // [n][t*2+k]
__device__ float d_AX[NN * (TT * INP)];     // A @ Xall
__device__ float d_W0[132 * G4];            // k: h0(64) Ah0(64) x(2) Ax(2)
__device__ float d_W1[256 * G4];            // k: h0(64) Ah0(64) h1(64) Ah1(64)
__device__ float d_b0[G4];
__device__ float d_b1[G4];
__device__ int   d_rowcnt[NN];
__device__ int   d_rowptr[NN + 1];
__device__ float d_dinv[NN];
__device__ int   d_col[MAXNNZ];
__device__ float d_val[MAXNNZ];

// ---------------- helpers ----------------
__device__ __forceinline__ ull fma2(ull a, ull b, ull c) {
    ull d;
    asm("fma.rn.f32x2 %0, %1, %2, %3;" : "=l"(d) : "l"(a), "l"(b), "l"(c));
    return d;
}
__device__ __forceinline__ float sigf(float v) {
    return __fdividef(1.f, 1.f + __expf(-v));
}
__device__ __forceinline__ float tanhfast(float v) {
    return __fmaf_rn(2.f, __fdividef(1.f, 1.f + __expf(-2.f * v)), -1.f);
}

// ---------------- setup kernel 1: degree count + all prep work ----------------
__global__ void k_degprep(const float* __restrict__ adj, const float* __restrict__ x,
                          const float* __restrict__ gcWi0, const float* __restrict__ gcbi0,
                          const float* __restrict__ gcWh0, const float* __restrict__ gcbh0,
                          const float* __restrict__ liWi0, const float* __restrict__ libi0,
                          const float* __restrict__ liWh0, const float* __restrict__ libh0,
                          const float* __restrict__ gcWi1, const float* __restrict__ gcbi1,
                          const float* __restrict__ gcWh1, const float* __restrict__ gcbh1,
                          const float* __restrict__ liWi1, const float* __restrict__ libi1,
                          const float* __restrict__ liWh1, const float* __restrict__ libh1) {
    int i = blockIdx.x;
    int tid = threadIdx.x;
    // ---- degree + nnz count for row i ----
    {
        const float* row = adj + (size_t)i * NN;
        int cnt = 0; float deg = 0.f;
        for (int j = tid; j < NN; j += 256) {
            float a = row[j];
            if (j == i) a += 1.f;
            if (a != 0.f) { cnt++; deg += a; }
        }
        __shared__ int   scnt[256];
        __shared__ float sdeg[256];
        scnt[tid] = cnt; sdeg[tid] = deg;
        __syncthreads();
        for (int s = 128; s > 0; s >>= 1) {
            if (tid < s) { scnt[tid] += scnt[tid + s]; sdeg[tid] += sdeg[tid + s]; }
            __syncthreads();
        }
        if (tid == 0) {
            d_rowcnt[i] = scnt[0];
            d_dinv[i] = rsqrtf(sdeg[0]);
        }
    }
    // ---- prep work (grid covers 1M ids) ----
    int id = i * 256 + tid;
    if (id < NN * (TT * INP)) {
        int n = id / (TT * INP), c = id % (TT * INP);
        int t = c >> 1, k = c & 1;
        d_Xall[id] = x[t * (NN * INP) + n * INP + k];
    }
    if (id < NN * HC) {
        d_hcat[0][id] = 0.f;        // h1 half matters; h0 half overwritten later
    }
    if (id < NN * HH) {
        d_c1[id] = 0.f;
    }
    if (id < 256 * G4) {
        int k = id >> 8, c = id & 255;
        float w1;
        if (k < 64)       w1 = liWi1[k * G4 + c];
        else if (k < 128) w1 = gcWi1[(k - 64) * G4 + c];
        else if (k < 192) w1 = liWh1[(k - 128) * G4 + c];
        else              w1 = gcWh1[(k - 192) * G4 + c];
        d_W1[id] = w1;
        if (k < 132) {
            float w0;
            if (k < 64)       w0 = liWh0[k * G4 + c];
            else if (k < 128) w0 = gcWh0[(k - 64) * G4 + c];
            else if (k < 130) w0 = liWi0[(k - 128) * G4 + c];
            else              w0 = gcWi0[(k - 130) * G4 + c];
            d_W0[k * G4 + c] = w0;
        }
        if (id < G4) {
            d_b0[id] = gcbi0[id] + gcbh0[id] + libi0[id] + libh0[id];
            d_b1[id] = gcbi1[id] + gcbh1[id] + libi1[id] + libh1[id];
        }
    }
}

// ---------------- setup kernel 2: exclusive scan ----------------
__global__ void k_scan() {
    __shared__ int ssum[1024];
    int t = threadIdx.x;
    int c0 = d_rowcnt[4 * t], c1 = d_rowcnt[4 * t + 1],
        c2 = d_rowcnt[4 * t + 2], c3 = d_rowcnt[4 * t + 3];
    int s = c0 + c1 + c2 + c3;
    ssum[t] = s;
    __syncthreads();
    for (int off = 1; off < 1024; off <<= 1) {
        int v = (t >= off) ? ssum[t - off] : 0;
        __syncthreads();
        ssum[t] += v;
        __syncthreads();
    }
    int excl = ssum[t] - s;
    d_rowptr[4 * t]     = excl;
    d_rowptr[4 * t + 1] = excl + c0;
    d_rowptr[4 * t + 2] = excl + c0 + c1;
    d_rowptr[4 * t + 3] = excl + c0 + c1 + c2;
    if (t == 1023) d_rowptr[NN] = ssum[1023];
}

// ---------------- setup kernel 3: CSR fill + AX spmm (own row) + first-step cell0 ----------------
__global__ void k_fillx(const float* __restrict__ adj, const float* __restrict__ x) {
    int i = blockIdx.x;
    int tid = threadIdx.x;
    const float* row = adj + (size_t)i * NN;
    float di = d_dinv[i];
    int cnt = 0;
    for (int j = tid * 16; j < tid * 16 + 16; j++) {
        float a = row[j] + ((j == i) ? 1.f : 0.f);
        if (a != 0.f) cnt++;
    }
    __shared__ int soff[256];
    __shared__ float sax[2];
    soff[tid] = cnt;
    __syncthreads();
    for (int off = 1; off < 256; off <<= 1) {
        int v = (tid >= off) ? soff[tid - off] : 0;
        __syncthreads();
        soff[tid] += v;
        __syncthreads();
    }
    int pos = d_rowptr[i] + soff[tid] - cnt;
    for (int j = tid * 16; j < tid * 16 + 16; j++) {
        float a = row[j] + ((j == i) ? 1.f : 0.f);
        if (a != 0.f) {
            d_col[pos] = j;
            d_val[pos] = di * a * d_dinv[j];
            pos++;
        }
    }
    __syncthreads();   // row i's CSR fully written, visible to this block

    // ---- AX row i (threads 0..95) ----
    if (tid < TT * INP) {
        int p0 = d_rowptr[i], p1 = d_rowptr[i + 1];
        float acc = 0.f;
        for (int p = p0; p < p1; p++) {
            acc += d_val[p] * d_Xall[d_col[p] * (TT * INP) + tid];
        }
        d_AX[i * (TT * INP) + tid] = acc;
        if (tid < 2) sax[tid] = acc;
    }
    __syncthreads();

    // ---- first-step cell0 for node i (h0=Ah0=0 so comb = b0 + x-part) ----
    if (tid < HH) {
        int j = tid;
        float x0  = x[i * INP];
        float x1  = x[i * INP + 1];
        float ax0 = sax[0];
        float ax1 = sax[1];
        float gv[4];
        #pragma unroll
        for (int q = 0; q < 4; q++) {
            int c = q * 64 + j;
            gv[q] = d_b0[c]
                  + x0  * d_W0[128 * G4 + c] + x1  * d_W0[129 * G4 + c]
                  + ax0 * d_W0[130 * G4 + c] + ax1 * d_W0[131 * G4 + c];
        }
        float nc = sigf(gv[0]) * tanhfast(gv[3]);
        float nh = sigf(gv[2]) * tanhfast(nc);
        d_c0[i * HH + j] = nc;
        d_hcat[0][i * HC + j] = nh;
    }
}

// ---------------- GEMM: split-K broadcast-z (512 threads, 16 warps) ----------------
// half = w>>3 selects k range [half*K/2, (half+1)*K/2)
// ws = w&7: rows r0=(ws&3)*4 .. +3, cols c0=(ws>>2)*128 + lane*4 .. +3
// half 0 seeds bias, half 1 seeds zero; partials land in comb[half]
template <int K>
__device__ __forceinline__ void gemm_block(const float* __restrict__ sh, float* __restrict__ comb,
                                           const float* __restrict__ W,
                                           const float* __restrict__ bb, int tid) {
    constexpr int KH = K / 2;
    int w = tid >> 5, lane = tid & 31;
    int half = w >> 3;
    int ws = w & 7;
    int r0 = (ws & 3) << 2;
    int c0 = ((ws >> 2) << 7) + (lane << 2);
    const float* Wp = W + half * KH * G4 + c0;
    const ull* zz = (const ull*)sh + half * KH * 17 + r0;

    ull a00, a01, a10, a11, a20, a21, a30, a31;
    if (half == 0) {
        ulonglong2 b2 = *(const ulonglong2*)(bb + c0);
        a00 = b2.x; a01 = b2.y; a10 = b2.x; a11 = b2.y;
        a20 = b2.x; a21 = b2.y; a30 = b2.x; a31 = b2.y;
    } else {
        a00 = a01 = a10 = a11 = a20 = a21 = a30 = a31 = 0ull;
    }

    #pragma unroll 4
    for (int k = 0; k < KH; k++) {
        ulonglong2 w2 = *(const ulonglong2*)(Wp + k * G4);
        ull z0 = zz[k * 17];        // broadcast loads (same addr across warp)
        ull z1 = zz[k * 17 + 1];
        ull z2 = zz[k * 17 + 2];
        ull z3 = zz[k * 17 + 3];
        a00 = fma2(z0, w2.x, a00); a01 = fma2(z0, w2.y, a01);
        a10 = fma2(z1, w2.x, a10); a11 = fma2(z1, w2.y, a11);
        a20 = fma2(z2, w2.x, a20); a21 = fma2(z2, w2.y, a21);
        a30 = fma2(z3, w2.x, a30); a31 = fma2(z3, w2.y, a31);
    }
    float* base = comb + half * (RPB * G4) + r0 * G4 + c0;
    *(ulonglong2*)(base)          = make_ulonglong2(a00, a01);
    *(ulonglong2*)(base + G4)     = make_ulonglong2(a10, a11);
    *(ulonglong2*)(base + 2 * G4) = make_ulonglong2(a20, a21);
    *(ulonglong2*)(base + 3 * G4) = make_ulonglong2(a30, a31);
}

// ---------------- gates: comb(2 halves) -> c,h ----------------
__device__ __forceinline__ void gates_block(const float* __restrict__ comb,
                                            float* __restrict__ cstate,
                                            float* __restrict__ hdst,
                                            int hoff, int n0, int tid) {
    const float* combB = comb + RPB * G4;
    #pragma unroll
    for (int i = 0; i < 2; i++) {
        int e = i * NTH + tid;          // 1024 = 16 rows * 64
        int r = e >> 6, j = e & 63;
        float ig = comb[r * G4 + j]       + combB[r * G4 + j];
        float fg = comb[r * G4 + 64 + j]  + combB[r * G4 + 64 + j];
        float og = comb[r * G4 + 128 + j] + combB[r * G4 + 128 + j];
        float gg = comb[r * G4 + 192 + j] + combB[r * G4 + 192 + j];
        int n = n0 + r;
        float cold = cstate[n * HH + j];
        float nc = sigf(fg) * cold + sigf(ig) * tanhfast(gg);
        float nh = sigf(og) * tanhfast(nc);
        cstate[n * HH + j] = nc;
        hdst[n * HC + hoff + j] = nh;
    }
}

// ---------------- fused step: cell1(t) then cell0(t+1) ----------------
__global__ void __launch_bounds__(NTH) k_fused(const float* __restrict__ x, int t) {
    extern __shared__ float sh[];
    float* comb = sh + 256 * ZS;
    int tid = threadIdx.x;
    int n0 = blockIdx.x * RPB;
    int cur = t & 1, nxt = cur ^ 1;
    const float* __restrict__ g = d_hcat[cur];

    // ---- plain z rows (h0 -> k 0..63, h1 -> k 128..191), duplicated pairs ----
    #pragma unroll
    for (int i = 0; i < 2; i++) {
        int e = i * NTH + tid;          // [0, 1024) = 16 rows x 64 k
        int r = e >> 6, k = e & 63;
        float v1 = g[(n0 + r) * HC + k];
        float v2 = g[(n0 + r) * HC + 64 + k];
        *(float2*)(sh + k * ZS + 2 * r)         = make_float2(v1, v1);
        *(float2*)(sh + (128 + k) * ZS + 2 * r) = make_float2(v2, v2);
    }

    // ---- gather: A@h0 -> k 64..127, A@h1 -> k 192..255 (16 warps, 1 row each) ----
    {
        int w = tid >> 5, lane = tid & 31;
        int koff = ((lane < 16) ? 64 : 128) + 4 * lane;
        const float* gl = g + 4 * lane;
        int n = n0 + w;
        int p = d_rowptr[n], p1 = d_rowptr[n + 1];
        float a0 = 0.f, a1 = 0.f, a2 = 0.f, a3 = 0.f;
        for (; p + 4 <= p1; p += 4) {
            int   m0 = d_col[p],     m1 = d_col[p + 1];
            int   m2 = d_col[p + 2], m3 = d_col[p + 3];
            float v0 = d_val[p],     v1 = d_val[p + 1];
            float v2 = d_val[p + 2], v3 = d_val[p + 3];
            float4 A = *(const float4*)(gl + m0 * HC);
            float4 B = *(const float4*)(gl + m1 * HC);
            float4 C = *(const float4*)(gl + m2 * HC);
            float4 D = *(const float4*)(gl + m3 * HC);
            a0 += v0 * A.x; a1 += v0 * A.y; a2 += v0 * A.z; a3 += v0 * A.w;
            a0 += v1 * B.x; a1 += v1 * B.y; a2 += v1 * B.z; a3 += v1 * B.w;
            a0 += v2 * C.x; a1 += v2 * C.y; a2 += v2 * C.z; a3 += v2 * C.w;
            a0 += v3 * D.x; a1 += v3 * D.y; a2 += v3 * D.z; a3 += v3 * D.w;
        }
        for (; p < p1; p++) {
            int m = d_col[p];
            float v = d_val[p];
            float4 A = *(const float4*)(gl + m * HC);
            a0 += v * A.x; a1 += v * A.y; a2 += v * A.z; a3 += v * A.w;
        }
        *(float2*)(sh + (koff + 0) * ZS + 2 * w) = make_float2(a0, a0);
        *(float2*)(sh + (koff + 1) * ZS + 2 * w) = make_float2(a1, a1);
        *(float2*)(sh + (koff + 2) * ZS + 2 * w) = make_float2(a2, a2);
        *(float2*)(sh + (koff + 3) * ZS + 2 * w) = make_float2(a3, a3);
    }
    __syncthreads();

    // ---- cell1 GEMM (K=256, split) + gates -> h1(t), c1 ----
    gemm_block<256>(sh, comb, d_W1, d_b1, tid);
    __syncthreads();
    gates_block(comb, d_c1, d_hcat[nxt], 64, n0, tid);
    __syncthreads();

    // ---- cell0(t+1): reuse z k 0..127; overwrite k 128..131 with x(t+1) ----
    if (t + 1 < TT) {
        if (tid < RPB) {
            int n = n0 + tid;
            float x0  = x[(t + 1) * (NN * INP) + n * INP];
            float x1  = x[(t + 1) * (NN * INP) + n * INP + 1];
            float ax0 = d_AX[n * (TT * INP) + 2 * (t + 1)];
            float ax1 = d_AX[n * (TT * INP) + 2 * (t + 1) + 1];
            *(float2*)(sh + 128 * ZS + 2 * tid) = make_float2(x0, x0);
            *(float2*)(sh + 129 * ZS + 2 * tid) = make_float2(x1, x1);
            *(float2*)(sh + 130 * ZS + 2 * tid) = make_float2(ax0, ax0);
            *(float2*)(sh + 131 * ZS + 2 * tid) = make_float2(ax1, ax1);
        }
        __syncthreads();
        gemm_block<132>(sh, comb, d_W0, d_b0, tid);
        __syncthreads();
        gates_block(comb, d_c0, d_hcat[nxt], 0, n0, tid);
    }
}

// ---------------- output projection ----------------
__global__ void k_out(const float* __restrict__ outW, const float* __restrict__ outb,
                      float* __restrict__ out) {
    int gidx = blockIdx.x * blockDim.x + threadIdx.x;
    if (gidx >= NN * PP) return;
    int n = gidx / PP, p = gidx % PP;
    const float* h = d_hcat[TT & 1] + n * HC + 64;
    float acc = outb[p];
    #pragma unroll
    for (int k = 0; k < HH; k++) acc += h[k] * outW[k * PP + p];
    out[gidx] = acc;
}

extern "C" void kernel_launch(void* const* d_in, const int* in_sizes, int n_in,
                              void* d_out, int out_size) {
    const float* x     = (const float*)d_in[0];
    const float* adj   = (const float*)d_in[1];
    const float* gcWi0 = (const float*)d_in[2];
    const float* gcbi0 = (const float*)d_in[3];
    const float* gcWh0 = (const float*)d_in[4];
    const float* gcbh0 = (const float*)d_in[5];
    const float* liWi0 = (const float*)d_in[6];
    const float* libi0 = (const float*)d_in[7];
    const float* liWh0 = (const float*)d_in[8];
    const float* libh0 = (const float*)d_in[9];
    const float* gcWi1 = (const float*)d_in[10];
    const float* gcbi1 = (const float*)d_in[11];
    const float* gcWh1 = (const float*)d_in[12];
    const float* gcbh1 = (const float*)d_in[13];
    const float* liWi1 = (const float*)d_in[14];
    const float* libi1 = (const float*)d_in[15];
    const float* liWh1 = (const float*)d_in[16];
    const float* libh1 = (const float*)d_in[17];
    const float* outW  = (const float*)d_in[18];
    const float* outb  = (const float*)d_in[19];
    float* out = (float*)d_out;

    static int smem_set = 0;
    if (!smem_set) {
        cudaFuncSetAttribute(k_fused, cudaFuncAttributeMaxDynamicSharedMemorySize, SMEM_FUSED);
        smem_set = 1;
    }

    k_degprep<<<4096, 256>>>(adj, x, gcWi0, gcbi0, gcWh0, gcbh0, liWi0, libi0, liWh0, libh0,
                             gcWi1, gcbi1, gcWh1, gcbh1, liWi1, libi1, liWh1, libh1);
    k_scan<<<1, 1024>>>();
    k_fillx<<<NN, 256>>>(adj, x);
    for (int t = 0; t < TT; t++) {
        k_fused<<<NN / RPB, NTH, SMEM_FUSED>>>(x, t);
    }
    k_out<<<(NN * PP + 255) / 256, 256>>>(outW, outb, out);
}

// round 11
// speedup vs baseline: 1.1362x; 1.1362x over previous
#include <cuda_runtime.h>
#include <math.h>

#define NN 4096
#define HH 64
#define HC 128          // concatenated row width: [h0(64) | h1(64)]
#define G4 256
#define TT 48
#define INP 2
#define PP 12
#define RPB 16          // rows per block
#define NTH 256
#define ZS 36           // shared z stride per k in floats (32 duplicated + 4 pad) -> 18 ull (EVEN: ull2-aligned)
#define SMEM_FUSED ((256 * ZS + RPB * G4) * 4)   // z tile (36.9KB) + comb (16KB) = 52KB
#define MAXNNZ (1 << 21)

typedef unsigned long long ull;

// ---------------- static device scratch ----------------
__device__ float d_hcat[2][NN * HC];        // ping-pong [h0 | h1] per node
__device__ float d_c0[NN * HH];
__device__ float d_c1[NN * HH];
__device__ float d_Xall[NN * (TT * INP)];   // [n][t*2+k]
__device__ float d_AX[NN * (TT * INP)];     // A @ Xall
__device__ float d_W0[132 * G4];            // k: h0(64) Ah0(64) x(2) Ax(2)
__device__ float d_W1[256 * G4];            // k: h0(64) Ah0(64) h1(64) Ah1(64)
__device__ float d_b0[G4];
__device__ float d_b1[G4];
__device__ int   d_rowcnt[NN];
__device__ int   d_rowptr[NN + 1];
__device__ float d_dinv[NN];
__device__ int   d_col[MAXNNZ];
__device__ float d_val[MAXNNZ];

// ---------------- helpers ----------------
__device__ __forceinline__ ull fma2(ull a, ull b, ull c) {
    ull d;
    asm("fma.rn.f32x2 %0, %1, %2, %3;" : "=l"(d) : "l"(a), "l"(b), "l"(c));
    return d;
}
__device__ __forceinline__ float sigf(float v) {
    return __fdividef(1.f, 1.f + __expf(-v));
}
__device__ __forceinline__ float tanhfast(float v) {
    return __fmaf_rn(2.f, __fdividef(1.f, 1.f + __expf(-2.f * v)), -1.f);
}

// ---------------- setup kernel 1: degree count + all prep work ----------------
__global__ void k_degprep(const float* __restrict__ adj, const float* __restrict__ x,
                          const float* __restrict__ gcWi0, const float* __restrict__ gcbi0,
                          const float* __restrict__ gcWh0, const float* __restrict__ gcbh0,
                          const float* __restrict__ liWi0, const float* __restrict__ libi0,
                          const float* __restrict__ liWh0, const float* __restrict__ libh0,
                          const float* __restrict__ gcWi1, const float* __restrict__ gcbi1,
                          const float* __restrict__ gcWh1, const float* __restrict__ gcbh1,
                          const float* __restrict__ liWi1, const float* __restrict__ libi1,
                          const float* __restrict__ liWh1, const float* __restrict__ libh1) {
    int i = blockIdx.x;
    int tid = threadIdx.x;
    // ---- degree + nnz count for row i ----
    {
        const float* row = adj + (size_t)i * NN;
        int cnt = 0; float deg = 0.f;
        for (int j = tid; j < NN; j += 256) {
            float a = row[j];
            if (j == i) a += 1.f;
            if (a != 0.f) { cnt++; deg += a; }
        }
        __shared__ int   scnt[256];
        __shared__ float sdeg[256];
        scnt[tid] = cnt; sdeg[tid] = deg;
        __syncthreads();
        for (int s = 128; s > 0; s >>= 1) {
            if (tid < s) { scnt[tid] += scnt[tid + s]; sdeg[tid] += sdeg[tid + s]; }
            __syncthreads();
        }
        if (tid == 0) {
            d_rowcnt[i] = scnt[0];
            d_dinv[i] = rsqrtf(sdeg[0]);
        }
    }
    // ---- prep work (grid covers 1M ids) ----
    int id = i * 256 + tid;
    if (id < NN * (TT * INP)) {
        int n = id / (TT * INP), c = id % (TT * INP);
        int t = c >> 1, k = c & 1;
        d_Xall[id] = x[t * (NN * INP) + n * INP + k];
    }
    if (id < NN * HC) {
        d_hcat[0][id] = 0.f;        // h1 half matters; h0 half overwritten later
    }
    if (id < NN * HH) {
        d_c1[id] = 0.f;
    }
    if (id < 256 * G4) {
        int k = id >> 8, c = id & 255;
        float w1;
        if (k < 64)       w1 = liWi1[k * G4 + c];
        else if (k < 128) w1 = gcWi1[(k - 64) * G4 + c];
        else if (k < 192) w1 = liWh1[(k - 128) * G4 + c];
        else              w1 = gcWh1[(k - 192) * G4 + c];
        d_W1[id] = w1;
        if (k < 132) {
            float w0;
            if (k < 64)       w0 = liWh0[k * G4 + c];
            else if (k < 128) w0 = gcWh0[(k - 64) * G4 + c];
            else if (k < 130) w0 = liWi0[(k - 128) * G4 + c];
            else              w0 = gcWi0[(k - 130) * G4 + c];
            d_W0[k * G4 + c] = w0;
        }
        if (id < G4) {
            d_b0[id] = gcbi0[id] + gcbh0[id] + libi0[id] + libh0[id];
            d_b1[id] = gcbi1[id] + gcbh1[id] + libi1[id] + libh1[id];
        }
    }
}

// ---------------- setup kernel 2: exclusive scan ----------------
__global__ void k_scan() {
    __shared__ int ssum[1024];
    int t = threadIdx.x;
    int c0 = d_rowcnt[4 * t], c1 = d_rowcnt[4 * t + 1],
        c2 = d_rowcnt[4 * t + 2], c3 = d_rowcnt[4 * t + 3];
    int s = c0 + c1 + c2 + c3;
    ssum[t] = s;
    __syncthreads();
    for (int off = 1; off < 1024; off <<= 1) {
        int v = (t >= off) ? ssum[t - off] : 0;
        __syncthreads();
        ssum[t] += v;
        __syncthreads();
    }
    int excl = ssum[t] - s;
    d_rowptr[4 * t]     = excl;
    d_rowptr[4 * t + 1] = excl + c0;
    d_rowptr[4 * t + 2] = excl + c0 + c1;
    d_rowptr[4 * t + 3] = excl + c0 + c1 + c2;
    if (t == 1023) d_rowptr[NN] = ssum[1023];
}

// ---------------- setup kernel 3: CSR fill + AX spmm (own row) + first-step cell0 ----------------
__global__ void k_fillx(const float* __restrict__ adj, const float* __restrict__ x) {
    int i = blockIdx.x;
    int tid = threadIdx.x;
    const float* row = adj + (size_t)i * NN;
    float di = d_dinv[i];
    int cnt = 0;
    for (int j = tid * 16; j < tid * 16 + 16; j++) {
        float a = row[j] + ((j == i) ? 1.f : 0.f);
        if (a != 0.f) cnt++;
    }
    __shared__ int soff[256];
    __shared__ float sax[2];
    soff[tid] = cnt;
    __syncthreads();
    for (int off = 1; off < 256; off <<= 1) {
        int v = (tid >= off) ? soff[tid - off] : 0;
        __syncthreads();
        soff[tid] += v;
        __syncthreads();
    }
    int pos = d_rowptr[i] + soff[tid] - cnt;
    for (int j = tid * 16; j < tid * 16 + 16; j++) {
        float a = row[j] + ((j == i) ? 1.f : 0.f);
        if (a != 0.f) {
            d_col[pos] = j;
            d_val[pos] = di * a * d_dinv[j];
            pos++;
        }
    }
    __syncthreads();   // row i's CSR fully written, visible to this block

    // ---- AX row i (threads 0..95) ----
    if (tid < TT * INP) {
        int p0 = d_rowptr[i], p1 = d_rowptr[i + 1];
        float acc = 0.f;
        for (int p = p0; p < p1; p++) {
            acc += d_val[p] * d_Xall[d_col[p] * (TT * INP) + tid];
        }
        d_AX[i * (TT * INP) + tid] = acc;
        if (tid < 2) sax[tid] = acc;
    }
    __syncthreads();

    // ---- first-step cell0 for node i (h0=Ah0=0 so comb = b0 + x-part) ----
    if (tid < HH) {
        int j = tid;
        float x0  = x[i * INP];
        float x1  = x[i * INP + 1];
        float ax0 = sax[0];
        float ax1 = sax[1];
        float gv[4];
        #pragma unroll
        for (int q = 0; q < 4; q++) {
            int c = q * 64 + j;
            gv[q] = d_b0[c]
                  + x0  * d_W0[128 * G4 + c] + x1  * d_W0[129 * G4 + c]
                  + ax0 * d_W0[130 * G4 + c] + ax1 * d_W0[131 * G4 + c];
        }
        float nc = sigf(gv[0]) * tanhfast(gv[3]);
        float nh = sigf(gv[2]) * tanhfast(nc);
        d_c0[i * HH + j] = nc;
        d_hcat[0][i * HC + j] = nh;
    }
}

// ---------------- GEMM: broadcast-z via ulonglong2 (256 threads, 8 warps) ----------------
// warp w: rows r0=(w&3)*4 .. +3, cols c0=(w>>2)*128 + lane*4 .. +3
// z duplicated in sh: ull slot (k*18 + r) = {z[r][k], z[r][k]}; 18 even -> ull2 aligned.
// Per k: 1 LDG.128 (W) + 2 LDS.128 broadcast (4 z rows) + 8 FFMA2.
template <int K>
__device__ __forceinline__ void gemm_block(const float* __restrict__ sh, float* __restrict__ comb,
                                           const float* __restrict__ W,
                                           const float* __restrict__ bb, int tid) {
    int w = tid >> 5, lane = tid & 31;
    int r0 = (w & 3) << 2;
    int c0 = ((w >> 2) << 7) + (lane << 2);
    const float* Wp = W + c0;
    const ull* zz = (const ull*)sh + r0;

    ulonglong2 b2 = *(const ulonglong2*)(bb + c0);
    ull a00 = b2.x, a01 = b2.y;
    ull a10 = b2.x, a11 = b2.y;
    ull a20 = b2.x, a21 = b2.y;
    ull a30 = b2.x, a31 = b2.y;

    #pragma unroll 4
    for (int k = 0; k < K; k++) {
        ulonglong2 w2 = *(const ulonglong2*)(Wp + k * G4);
        ulonglong2 zA = *(const ulonglong2*)(zz + k * 18);       // rows r0, r0+1 (broadcast)
        ulonglong2 zB = *(const ulonglong2*)(zz + k * 18 + 2);   // rows r0+2, r0+3
        a00 = fma2(zA.x, w2.x, a00); a01 = fma2(zA.x, w2.y, a01);
        a10 = fma2(zA.y, w2.x, a10); a11 = fma2(zA.y, w2.y, a11);
        a20 = fma2(zB.x, w2.x, a20); a21 = fma2(zB.x, w2.y, a21);
        a30 = fma2(zB.y, w2.x, a30); a31 = fma2(zB.y, w2.y, a31);
    }
    float* base = comb + r0 * G4 + c0;
    *(ulonglong2*)(base)          = make_ulonglong2(a00, a01);
    *(ulonglong2*)(base + G4)     = make_ulonglong2(a10, a11);
    *(ulonglong2*)(base + 2 * G4) = make_ulonglong2(a20, a21);
    *(ulonglong2*)(base + 3 * G4) = make_ulonglong2(a30, a31);
}

// ---------------- gates: comb -> c,h ----------------
__device__ __forceinline__ void gates_block(const float* __restrict__ comb,
                                            float* __restrict__ cstate,
                                            float* __restrict__ hdst,
                                            int hoff, int n0, int tid) {
    #pragma unroll
    for (int i = 0; i < 4; i++) {
        int e = i * NTH + tid;          // 1024 = 16 rows * 64
        int r = e >> 6, j = e & 63;
        float ig = comb[r * G4 + j];
        float fg = comb[r * G4 + 64 + j];
        float og = comb[r * G4 + 128 + j];
        float gg = comb[r * G4 + 192 + j];
        int n = n0 + r;
        float cold = cstate[n * HH + j];
        float nc = sigf(fg) * cold + sigf(ig) * tanhfast(gg);
        float nh = sigf(og) * tanhfast(nc);
        cstate[n * HH + j] = nc;
        hdst[n * HC + hoff + j] = nh;
    }
}

// ---------------- fused step: cell1(t) then cell0(t+1) ----------------
__global__ void __launch_bounds__(NTH) k_fused(const float* __restrict__ x, int t) {
    extern __shared__ float sh[];
    float* comb = sh + 256 * ZS;
    int tid = threadIdx.x;
    int n0 = blockIdx.x * RPB;
    int cur = t & 1, nxt = cur ^ 1;
    const float* __restrict__ g = d_hcat[cur];

    // ---- plain z rows (h0 -> k 0..63, h1 -> k 128..191), duplicated pairs ----
    #pragma unroll
    for (int i = 0; i < 4; i++) {
        int e = i * NTH + tid;
        int r = e >> 6, k = e & 63;
        float v1 = g[(n0 + r) * HC + k];
        float v2 = g[(n0 + r) * HC + 64 + k];
        *(float2*)(sh + k * ZS + 2 * r)         = make_float2(v1, v1);
        *(float2*)(sh + (128 + k) * ZS + 2 * r) = make_float2(v2, v2);
    }

    // ---- gather: A@h0 -> k 64..127, A@h1 -> k 192..255 (8 warps x 2 rows) ----
    {
        int w = tid >> 5, lane = tid & 31;
        int koff = ((lane < 16) ? 64 : 128) + 4 * lane;
        const float* gl = g + 4 * lane;
        #pragma unroll
        for (int half = 0; half < 2; half++) {
            int rr = w + half * 8;
            int n = n0 + rr;
            int p = d_rowptr[n], p1 = d_rowptr[n + 1];
            float a0 = 0.f, a1 = 0.f, a2 = 0.f, a3 = 0.f;
            for (; p + 4 <= p1; p += 4) {
                int   m0 = d_col[p],     m1 = d_col[p + 1];
                int   m2 = d_col[p + 2], m3 = d_col[p + 3];
                float v0 = d_val[p],     v1 = d_val[p + 1];
                float v2 = d_val[p + 2], v3 = d_val[p + 3];
                float4 A = *(const float4*)(gl + m0 * HC);
                float4 B = *(const float4*)(gl + m1 * HC);
                float4 C = *(const float4*)(gl + m2 * HC);
                float4 D = *(const float4*)(gl + m3 * HC);
                a0 += v0 * A.x; a1 += v0 * A.y; a2 += v0 * A.z; a3 += v0 * A.w;
                a0 += v1 * B.x; a1 += v1 * B.y; a2 += v1 * B.z; a3 += v1 * B.w;
                a0 += v2 * C.x; a1 += v2 * C.y; a2 += v2 * C.z; a3 += v2 * C.w;
                a0 += v3 * D.x; a1 += v3 * D.y; a2 += v3 * D.z; a3 += v3 * D.w;
            }
            for (; p < p1; p++) {
                int m = d_col[p];
                float v = d_val[p];
                float4 A = *(const float4*)(gl + m * HC);
                a0 += v * A.x; a1 += v * A.y; a2 += v * A.z; a3 += v * A.w;
            }
            *(float2*)(sh + (koff + 0) * ZS + 2 * rr) = make_float2(a0, a0);
            *(float2*)(sh + (koff + 1) * ZS + 2 * rr) = make_float2(a1, a1);
            *(float2*)(sh + (koff + 2) * ZS + 2 * rr) = make_float2(a2, a2);
            *(float2*)(sh + (koff + 3) * ZS + 2 * rr) = make_float2(a3, a3);
        }
    }
    __syncthreads();

    // ---- cell1 GEMM (K=256) + gates -> h1(t), c1 ----
    gemm_block<256>(sh, comb, d_W1, d_b1, tid);
    __syncthreads();
    gates_block(comb, d_c1, d_hcat[nxt], 64, n0, tid);
    __syncthreads();

    // ---- cell0(t+1): reuse z k 0..127; overwrite k 128..131 with x(t+1) ----
    if (t + 1 < TT) {
        if (tid < RPB) {
            int n = n0 + tid;
            float x0  = x[(t + 1) * (NN * INP) + n * INP];
            float x1  = x[(t + 1) * (NN * INP) + n * INP + 1];
            float ax0 = d_AX[n * (TT * INP) + 2 * (t + 1)];
            float ax1 = d_AX[n * (TT * INP) + 2 * (t + 1) + 1];
            *(float2*)(sh + 128 * ZS + 2 * tid) = make_float2(x0, x0);
            *(float2*)(sh + 129 * ZS + 2 * tid) = make_float2(x1, x1);
            *(float2*)(sh + 130 * ZS + 2 * tid) = make_float2(ax0, ax0);
            *(float2*)(sh + 131 * ZS + 2 * tid) = make_float2(ax1, ax1);
        }
        __syncthreads();
        gemm_block<132>(sh, comb, d_W0, d_b0, tid);
        __syncthreads();
        gates_block(comb, d_c0, d_hcat[nxt], 0, n0, tid);
    }
}

// ---------------- output projection ----------------
__global__ void k_out(const float* __restrict__ outW, const float* __restrict__ outb,
                      float* __restrict__ out) {
    int gidx = blockIdx.x * blockDim.x + threadIdx.x;
    if (gidx >= NN * PP) return;
    int n = gidx / PP, p = gidx % PP;
    const float* h = d_hcat[TT & 1] + n * HC + 64;
    float acc = outb[p];
    #pragma unroll
    for (int k = 0; k < HH; k++) acc += h[k] * outW[k * PP + p];
    out[gidx] = acc;
}

extern "C" void kernel_launch(void* const* d_in, const int* in_sizes, int n_in,
                              void* d_out, int out_size) {
    const float* x     = (const float*)d_in[0];
    const float* adj   = (const float*)d_in[1];
    const float* gcWi0 = (const float*)d_in[2];
    const float* gcbi0 = (const float*)d_in[3];
    const float* gcWh0 = (const float*)d_in[4];
    const float* gcbh0 = (const float*)d_in[5];
    const float* liWi0 = (const float*)d_in[6];
    const float* libi0 = (const float*)d_in[7];
    const float* liWh0 = (const float*)d_in[8];
    const float* libh0 = (const float*)d_in[9];
    const float* gcWi1 = (const float*)d_in[10];
    const float* gcbi1 = (const float*)d_in[11];
    const float* gcWh1 = (const float*)d_in[12];
    const float* gcbh1 = (const float*)d_in[13];
    const float* liWi1 = (const float*)d_in[14];
    const float* libi1 = (const float*)d_in[15];
    const float* liWh1 = (const float*)d_in[16];
    const float* libh1 = (const float*)d_in[17];
    const float* outW  = (const float*)d_in[18];
    const float* outb  = (const float*)d_in[19];
    float* out = (float*)d_out;

    static int smem_set = 0;
    if (!smem_set) {
        cudaFuncSetAttribute(k_fused, cudaFuncAttributeMaxDynamicSharedMemorySize, SMEM_FUSED);
        smem_set = 1;
    }

    k_degprep<<<4096, 256>>>(adj, x, gcWi0, gcbi0, gcWh0, gcbh0, liWi0, libi0, liWh0, libh0,
                             gcWi1, gcbi1, gcWh1, gcbh1, liWi1, libi1, liWh1, libh1);
    k_scan<<<1, 1024>>>();
    k_fillx<<<NN, 256>>>(adj, x);
    for (int t = 0; t < TT; t++) {
        k_fused<<<NN / RPB, NTH, SMEM_FUSED>>>(x, t);
    }
    k_out<<<(NN * PP + 255) / 256, 256>>>(outW, outb, out);
}

// round 12
// speedup vs baseline: 1.6523x; 1.4542x over previous
#include <cuda_runtime.h>
#include <math.h>

#define NN 4096
#define HH 64
#define HC 128          // concatenated row width: [h0(64) | h1(64)]
#define G4 256
#define TT 48
#define INP 2
#define PP 12
#define RPB 16          // rows per block
#define NTH 512         // 16 warps: 2 k-halves x 8 GEMM warps
#define ZS 36           // shared z stride per k in floats (32 dup + 4 pad) -> 18 ull (EVEN)
#define SMEM_FUSED ((256 * ZS + 2 * RPB * G4) * 4)   // z (36.9KB) + 2 comb (32KB) = 69KB
#define MAXNNZ (1 << 21)

typedef unsigned long long ull;

// ---------------- static device scratch ----------------
__device__ float d_hcat[2][NN * HC];        // ping-pong [h0 | h1] per node
__device__ float d_c0[NN * HH];
__device__ float d_c1[NN * HH];
__device__ float d_Xall[NN * (TT * INP)];   // [n][t*2+k]
__device__ float d_AX[NN * (TT * INP)];     // A @ Xall
__device__ float d_W0[132 * G4];            // k: h0(64) Ah0(64) x(2) Ax(2)
__device__ float d_W1[256 * G4];            // k: h0(64) Ah0(64) h1(64) Ah1(64)
__device__ float d_b0[G4];
__device__ float d_b1[G4];
__device__ int   d_rowcnt[NN];
__device__ int   d_rowptr[NN + 1];
__device__ float d_dinv[NN];
__device__ int   d_col[MAXNNZ];
__device__ float d_val[MAXNNZ];

// ---------------- helpers ----------------
__device__ __forceinline__ ull fma2(ull a, ull b, ull c) {
    ull d;
    asm("fma.rn.f32x2 %0, %1, %2, %3;" : "=l"(d) : "l"(a), "l"(b), "l"(c));
    return d;
}
__device__ __forceinline__ float sigf(float v) {
    return __fdividef(1.f, 1.f + __expf(-v));
}
__device__ __forceinline__ float tanhfast(float v) {
    return __fmaf_rn(2.f, __fdividef(1.f, 1.f + __expf(-2.f * v)), -1.f);
}

// ---------------- setup kernel 1: degree count + all prep work ----------------
__global__ void k_degprep(const float* __restrict__ adj, const float* __restrict__ x,
                          const float* __restrict__ gcWi0, const float* __restrict__ gcbi0,
                          const float* __restrict__ gcWh0, const float* __restrict__ gcbh0,
                          const float* __restrict__ liWi0, const float* __restrict__ libi0,
                          const float* __restrict__ liWh0, const float* __restrict__ libh0,
                          const float* __restrict__ gcWi1, const float* __restrict__ gcbi1,
                          const float* __restrict__ gcWh1, const float* __restrict__ gcbh1,
                          const float* __restrict__ liWi1, const float* __restrict__ libi1,
                          const float* __restrict__ liWh1, const float* __restrict__ libh1) {
    int i = blockIdx.x;
    int tid = threadIdx.x;
    // ---- degree + nnz count for row i ----
    {
        const float* row = adj + (size_t)i * NN;
        int cnt = 0; float deg = 0.f;
        for (int j = tid; j < NN; j += 256) {
            float a = row[j];
            if (j == i) a += 1.f;
            if (a != 0.f) { cnt++; deg += a; }
        }
        __shared__ int   scnt[256];
        __shared__ float sdeg[256];
        scnt[tid] = cnt; sdeg[tid] = deg;
        __syncthreads();
        for (int s = 128; s > 0; s >>= 1) {
            if (tid < s) { scnt[tid] += scnt[tid + s]; sdeg[tid] += sdeg[tid + s]; }
            __syncthreads();
        }
        if (tid == 0) {
            d_rowcnt[i] = scnt[0];
            d_dinv[i] = rsqrtf(sdeg[0]);
        }
    }
    // ---- prep work (grid covers 1M ids) ----
    int id = i * 256 + tid;
    if (id < NN * (TT * INP)) {
        int n = id / (TT * INP), c = id % (TT * INP);
        int t = c >> 1, k = c & 1;
        d_Xall[id] = x[t * (NN * INP) + n * INP + k];
    }
    if (id < NN * HC) {
        d_hcat[0][id] = 0.f;        // h1 half matters; h0 half overwritten later
    }
    if (id < NN * HH) {
        d_c1[id] = 0.f;
    }
    if (id < 256 * G4) {
        int k = id >> 8, c = id & 255;
        float w1;
        if (k < 64)       w1 = liWi1[k * G4 + c];
        else if (k < 128) w1 = gcWi1[(k - 64) * G4 + c];
        else if (k < 192) w1 = liWh1[(k - 128) * G4 + c];
        else              w1 = gcWh1[(k - 192) * G4 + c];
        d_W1[id] = w1;
        if (k < 132) {
            float w0;
            if (k < 64)       w0 = liWh0[k * G4 + c];
            else if (k < 128) w0 = gcWh0[(k - 64) * G4 + c];
            else if (k < 130) w0 = liWi0[(k - 128) * G4 + c];
            else              w0 = gcWi0[(k - 130) * G4 + c];
            d_W0[k * G4 + c] = w0;
        }
        if (id < G4) {
            d_b0[id] = gcbi0[id] + gcbh0[id] + libi0[id] + libh0[id];
            d_b1[id] = gcbi1[id] + gcbh1[id] + libi1[id] + libh1[id];
        }
    }
}

// ---------------- setup kernel 2: exclusive scan ----------------
__global__ void k_scan() {
    __shared__ int ssum[1024];
    int t = threadIdx.x;
    int c0 = d_rowcnt[4 * t], c1 = d_rowcnt[4 * t + 1],
        c2 = d_rowcnt[4 * t + 2], c3 = d_rowcnt[4 * t + 3];
    int s = c0 + c1 + c2 + c3;
    ssum[t] = s;
    __syncthreads();
    for (int off = 1; off < 1024; off <<= 1) {
        int v = (t >= off) ? ssum[t - off] : 0;
        __syncthreads();
        ssum[t] += v;
        __syncthreads();
    }
    int excl = ssum[t] - s;
    d_rowptr[4 * t]     = excl;
    d_rowptr[4 * t + 1] = excl + c0;
    d_rowptr[4 * t + 2] = excl + c0 + c1;
    d_rowptr[4 * t + 3] = excl + c0 + c1 + c2;
    if (t == 1023) d_rowptr[NN] = ssum[1023];
}

// ---------------- setup kernel 3: CSR fill + AX spmm (own row) + first-step cell0 ----------------
__global__ void k_fillx(const float* __restrict__ adj, const float* __restrict__ x) {
    int i = blockIdx.x;
    int tid = threadIdx.x;
    const float* row = adj + (size_t)i * NN;
    float di = d_dinv[i];
    int cnt = 0;
    for (int j = tid * 16; j < tid * 16 + 16; j++) {
        float a = row[j] + ((j == i) ? 1.f : 0.f);
        if (a != 0.f) cnt++;
    }
    __shared__ int soff[256];
    __shared__ float sax[2];
    soff[tid] = cnt;
    __syncthreads();
    for (int off = 1; off < 256; off <<= 1) {
        int v = (tid >= off) ? soff[tid - off] : 0;
        __syncthreads();
        soff[tid] += v;
        __syncthreads();
    }
    int pos = d_rowptr[i] + soff[tid] - cnt;
    for (int j = tid * 16; j < tid * 16 + 16; j++) {
        float a = row[j] + ((j == i) ? 1.f : 0.f);
        if (a != 0.f) {
            d_col[pos] = j;
            d_val[pos] = di * a * d_dinv[j];
            pos++;
        }
    }
    __syncthreads();   // row i's CSR fully written, visible to this block

    // ---- AX row i (threads 0..95) ----
    if (tid < TT * INP) {
        int p0 = d_rowptr[i], p1 = d_rowptr[i + 1];
        float acc = 0.f;
        for (int p = p0; p < p1; p++) {
            acc += d_val[p] * d_Xall[d_col[p] * (TT * INP) + tid];
        }
        d_AX[i * (TT * INP) + tid] = acc;
        if (tid < 2) sax[tid] = acc;
    }
    __syncthreads();

    // ---- first-step cell0 for node i (h0=Ah0=0 so comb = b0 + x-part) ----
    if (tid < HH) {
        int j = tid;
        float x0  = x[i * INP];
        float x1  = x[i * INP + 1];
        float ax0 = sax[0];
        float ax1 = sax[1];
        float gv[4];
        #pragma unroll
        for (int q = 0; q < 4; q++) {
            int c = q * 64 + j;
            gv[q] = d_b0[c]
                  + x0  * d_W0[128 * G4 + c] + x1  * d_W0[129 * G4 + c]
                  + ax0 * d_W0[130 * G4 + c] + ax1 * d_W0[131 * G4 + c];
        }
        float nc = sigf(gv[0]) * tanhfast(gv[3]);
        float nh = sigf(gv[2]) * tanhfast(nc);
        d_c0[i * HH + j] = nc;
        d_hcat[0][i * HC + j] = nh;
    }
}

// ---------------- GEMM: split-K + ull2 broadcast z (512 threads, 16 warps) ----------------
// half = w>>3 selects k range [half*K/2, (half+1)*K/2); partial -> comb[half]
// ws = w&7: rows r0=(ws&3)*4 .. +3, cols c0=(ws>>2)*128 + lane*4 .. +3
// Per warp-k: 1 LDG.128 (W) + 2 LDS.128 broadcast (4 z rows) + 8 FFMA2.
template <int K>
__device__ __forceinline__ void gemm_block(const float* __restrict__ sh, float* __restrict__ comb,
                                           const float* __restrict__ W,
                                           const float* __restrict__ bb, int tid) {
    constexpr int KH = K / 2;
    int w = tid >> 5, lane = tid & 31;
    int half = w >> 3;
    int ws = w & 7;
    int r0 = (ws & 3) << 2;
    int c0 = ((ws >> 2) << 7) + (lane << 2);
    const float* Wp = W + half * KH * G4 + c0;
    const ull* zz = (const ull*)sh + half * KH * 18 + r0;

    ull a00, a01, a10, a11, a20, a21, a30, a31;
    if (half == 0) {
        ulonglong2 b2 = *(const ulonglong2*)(bb + c0);
        a00 = b2.x; a01 = b2.y; a10 = b2.x; a11 = b2.y;
        a20 = b2.x; a21 = b2.y; a30 = b2.x; a31 = b2.y;
    } else {
        a00 = a01 = a10 = a11 = a20 = a21 = a30 = a31 = 0ull;
    }

    #pragma unroll 4
    for (int k = 0; k < KH; k++) {
        ulonglong2 w2 = *(const ulonglong2*)(Wp + k * G4);
        ulonglong2 zA = *(const ulonglong2*)(zz + k * 18);       // rows r0, r0+1 (broadcast)
        ulonglong2 zB = *(const ulonglong2*)(zz + k * 18 + 2);   // rows r0+2, r0+3
        a00 = fma2(zA.x, w2.x, a00); a01 = fma2(zA.x, w2.y, a01);
        a10 = fma2(zA.y, w2.x, a10); a11 = fma2(zA.y, w2.y, a11);
        a20 = fma2(zB.x, w2.x, a20); a21 = fma2(zB.x, w2.y, a21);
        a30 = fma2(zB.y, w2.x, a30); a31 = fma2(zB.y, w2.y, a31);
    }
    float* base = comb + half * (RPB * G4) + r0 * G4 + c0;
    *(ulonglong2*)(base)          = make_ulonglong2(a00, a01);
    *(ulonglong2*)(base + G4)     = make_ulonglong2(a10, a11);
    *(ulonglong2*)(base + 2 * G4) = make_ulonglong2(a20, a21);
    *(ulonglong2*)(base + 3 * G4) = make_ulonglong2(a30, a31);
}

// ---------------- gates: comb (2 halves) -> c,h ----------------
__device__ __forceinline__ void gates_block(const float* __restrict__ comb,
                                            float* __restrict__ cstate,
                                            float* __restrict__ hdst,
                                            int hoff, int n0, int tid) {
    const float* combB = comb + RPB * G4;
    #pragma unroll
    for (int i = 0; i < 2; i++) {
        int e = i * NTH + tid;          // 1024 = 16 rows * 64
        int r = e >> 6, j = e & 63;
        float ig = comb[r * G4 + j]       + combB[r * G4 + j];
        float fg = comb[r * G4 + 64 + j]  + combB[r * G4 + 64 + j];
        float og = comb[r * G4 + 128 + j] + combB[r * G4 + 128 + j];
        float gg = comb[r * G4 + 192 + j] + combB[r * G4 + 192 + j];
        int n = n0 + r;
        float cold = cstate[n * HH + j];
        float nc = sigf(fg) * cold + sigf(ig) * tanhfast(gg);
        float nh = sigf(og) * tanhfast(nc);
        cstate[n * HH + j] = nc;
        hdst[n * HC + hoff + j] = nh;
    }
}

// ---------------- fused step: cell1(t) then cell0(t+1) ----------------
__global__ void __launch_bounds__(NTH) k_fused(const float* __restrict__ x, int t) {
    extern __shared__ float sh[];
    float* comb = sh + 256 * ZS;
    int tid = threadIdx.x;
    int n0 = blockIdx.x * RPB;
    int cur = t & 1, nxt = cur ^ 1;
    const float* __restrict__ g = d_hcat[cur];

    // ---- plain z rows (h0 -> k 0..63, h1 -> k 128..191), duplicated pairs ----
    #pragma unroll
    for (int i = 0; i < 2; i++) {
        int e = i * NTH + tid;          // [0, 1024) = 16 rows x 64 k
        int r = e >> 6, k = e & 63;
        float v1 = g[(n0 + r) * HC + k];
        float v2 = g[(n0 + r) * HC + 64 + k];
        *(float2*)(sh + k * ZS + 2 * r)         = make_float2(v1, v1);
        *(float2*)(sh + (128 + k) * ZS + 2 * r) = make_float2(v2, v2);
    }

    // ---- gather: A@h0 -> k 64..127, A@h1 -> k 192..255 (16 warps x 1 row) ----
    {
        int w = tid >> 5, lane = tid & 31;
        int koff = ((lane < 16) ? 64 : 128) + 4 * lane;
        const float* gl = g + 4 * lane;
        int n = n0 + w;
        int p = d_rowptr[n], p1 = d_rowptr[n + 1];
        float a0 = 0.f, a1 = 0.f, a2 = 0.f, a3 = 0.f;
        for (; p + 4 <= p1; p += 4) {
            int   m0 = d_col[p],     m1 = d_col[p + 1];
            int   m2 = d_col[p + 2], m3 = d_col[p + 3];
            float v0 = d_val[p],     v1 = d_val[p + 1];
            float v2 = d_val[p + 2], v3 = d_val[p + 3];
            float4 A = *(const float4*)(gl + m0 * HC);
            float4 B = *(const float4*)(gl + m1 * HC);
            float4 C = *(const float4*)(gl + m2 * HC);
            float4 D = *(const float4*)(gl + m3 * HC);
            a0 += v0 * A.x; a1 += v0 * A.y; a2 += v0 * A.z; a3 += v0 * A.w;
            a0 += v1 * B.x; a1 += v1 * B.y; a2 += v1 * B.z; a3 += v1 * B.w;
            a0 += v2 * C.x; a1 += v2 * C.y; a2 += v2 * C.z; a3 += v2 * C.w;
            a0 += v3 * D.x; a1 += v3 * D.y; a2 += v3 * D.z; a3 += v3 * D.w;
        }
        for (; p < p1; p++) {
            int m = d_col[p];
            float v = d_val[p];
            float4 A = *(const float4*)(gl + m * HC);
            a0 += v * A.x; a1 += v * A.y; a2 += v * A.z; a3 += v * A.w;
        }
        *(float2*)(sh + (koff + 0) * ZS + 2 * w) = make_float2(a0, a0);
        *(float2*)(sh + (koff + 1) * ZS + 2 * w) = make_float2(a1, a1);
        *(float2*)(sh + (koff + 2) * ZS + 2 * w) = make_float2(a2, a2);
        *(float2*)(sh + (koff + 3) * ZS + 2 * w) = make_float2(a3, a3);
    }
    __syncthreads();

    // ---- cell1 GEMM (K=256, split-K) + gates -> h1(t), c1 ----
    gemm_block<256>(sh, comb, d_W1, d_b1, tid);
    __syncthreads();
    gates_block(comb, d_c1, d_hcat[nxt], 64, n0, tid);
    __syncthreads();

    // ---- cell0(t+1): reuse z k 0..127; overwrite k 128..131 with x(t+1) ----
    if (t + 1 < TT) {
        if (tid < RPB) {
            int n = n0 + tid;
            float x0  = x[(t + 1) * (NN * INP) + n * INP];
            float x1  = x[(t + 1) * (NN * INP) + n * INP + 1];
            float ax0 = d_AX[n * (TT * INP) + 2 * (t + 1)];
            float ax1 = d_AX[n * (TT * INP) + 2 * (t + 1) + 1];
            *(float2*)(sh + 128 * ZS + 2 * tid) = make_float2(x0, x0);
            *(float2*)(sh + 129 * ZS + 2 * tid) = make_float2(x1, x1);
            *(float2*)(sh + 130 * ZS + 2 * tid) = make_float2(ax0, ax0);
            *(float2*)(sh + 131 * ZS + 2 * tid) = make_float2(ax1, ax1);
        }
        __syncthreads();
        gemm_block<132>(sh, comb, d_W0, d_b0, tid);
        __syncthreads();
        gates_block(comb, d_c0, d_hcat[nxt], 0, n0, tid);
    }
}

// ---------------- output projection ----------------
__global__ void k_out(const float* __restrict__ outW, const float* __restrict__ outb,
                      float* __restrict__ out) {
    int gidx = blockIdx.x * blockDim.x + threadIdx.x;
    if (gidx >= NN * PP) return;
    int n = gidx / PP, p = gidx % PP;
    const float* h = d_hcat[TT & 1] + n * HC + 64;
    float acc = outb[p];
    #pragma unroll
    for (int k = 0; k < HH; k++) acc += h[k] * outW[k * PP + p];
    out[gidx] = acc;
}

extern "C" void kernel_launch(void* const* d_in, const int* in_sizes, int n_in,
                              void* d_out, int out_size) {
    const float* x     = (const float*)d_in[0];
    const float* adj   = (const float*)d_in[1];
    const float* gcWi0 = (const float*)d_in[2];
    const float* gcbi0 = (const float*)d_in[3];
    const float* gcWh0 = (const float*)d_in[4];
    const float* gcbh0 = (const float*)d_in[5];
    const float* liWi0 = (const float*)d_in[6];
    const float* libi0 = (const float*)d_in[7];
    const float* liWh0 = (const float*)d_in[8];
    const float* libh0 = (const float*)d_in[9];
    const float* gcWi1 = (const float*)d_in[10];
    const float* gcbi1 = (const float*)d_in[11];
    const float* gcWh1 = (const float*)d_in[12];
    const float* gcbh1 = (const float*)d_in[13];
    const float* liWi1 = (const float*)d_in[14];
    const float* libi1 = (const float*)d_in[15];
    const float* liWh1 = (const float*)d_in[16];
    const float* libh1 = (const float*)d_in[17];
    const float* outW  = (const float*)d_in[18];
    const float* outb  = (const float*)d_in[19];
    float* out = (float*)d_out;

    static int smem_set = 0;
    if (!smem_set) {
        cudaFuncSetAttribute(k_fused, cudaFuncAttributeMaxDynamicSharedMemorySize, SMEM_FUSED);
        smem_set = 1;
    }

    k_degprep<<<4096, 256>>>(adj, x, gcWi0, gcbi0, gcWh0, gcbh0, liWi0, libi0, liWh0, libh0,
                             gcWi1, gcbi1, gcWh1, gcbh1, liWi1, libi1, liWh1, libh1);
    k_scan<<<1, 1024>>>();
    k_fillx<<<NN, 256>>>(adj, x);
    for (int t = 0; t < TT; t++) {
        k_fused<<<NN / RPB, NTH, SMEM_FUSED>>>(x, t);
    }
    k_out<<<(NN * PP + 255) / 256, 256>>>(outW, outb, out);
}